// round 6
// baseline (speedup 1.0000x reference)
#include <cuda_runtime.h>
#include <math.h>

#define N_SAMP 32
#define C_TOT 256
#define CPG 16
#define GROUPS 16
#define NG 512
#define HW 4096
#define NHW (N_SAMP * HW)
#define TRI 136
#define STATS_LEN 152          // 16 sums + 136 tri
#define EPS 1e-5f
#define T_ITERS 5

#define K3_SPLIT 4
#define K3_POS (HW / K3_SPLIT)   // 1024

// -------- scratch (device globals) --------
__device__ float g_part[NG][STATS_LEN];   // per-(n,g): [0:16)=sums, [16:152)=tri
__device__ float g_bw[GROUPS][STATS_LEN]; // per-group batch sums
__device__ float g_A[NG][CPG * CPG];
__device__ float g_b0[NG][CPG];

// ------------------------------------------------------------------
// Kernel 1: stats. grid = NG blocks (one per (n,g)), 128 threads.
// Warps 0-1 (half 0): channel sums 0-7 + triangle rows 0-10 (66 accs)
// Warps 2-3 (half 1): channel sums 8-15 + triangle rows 11-15 (70 accs)
// Scalar loads (16 regs for v) to stay under the 128-reg cap; each
// half's 64 threads cover 64 positions per pass, 64 passes.
// ------------------------------------------------------------------
__global__ __launch_bounds__(128, 4) void stats_kernel(const float* __restrict__ x) {
    int ng = blockIdx.x;
    int n = ng >> 4;
    int g = ng & 15;
    int tid = threadIdx.x;
    int half = tid >> 6;       // 0 or 1
    int t = tid & 63;

    const float* __restrict__ xb = x + (size_t)(n * C_TOT + g * CPG) * HW;

    float s[8];
    float acc[70];
#pragma unroll
    for (int i = 0; i < 8; i++) s[i] = 0.f;
#pragma unroll
    for (int i = 0; i < 70; i++) acc[i] = 0.f;

#pragma unroll 2
    for (int pass = 0; pass < HW / 64; pass++) {
        int p = pass * 64 + t;
        float v[CPG];
#pragma unroll
        for (int c = 0; c < CPG; c++)
            v[c] = xb[(size_t)c * HW + p];

        if (half == 0) {
#pragma unroll
            for (int c = 0; c < 8; c++) s[c] += v[c];
            int idx = 0;
#pragma unroll
            for (int i = 0; i < 11; i++)
#pragma unroll
                for (int j = 0; j <= i; j++) {
                    acc[idx] += v[i] * v[j];
                    idx++;
                }
        } else {
#pragma unroll
            for (int c = 0; c < 8; c++) s[c] += v[c + 8];
            int idx = 0;
#pragma unroll
            for (int i = 11; i < 16; i++)
#pragma unroll
                for (int j = 0; j <= i; j++) {
                    acc[idx] += v[i] * v[j];
                    idx++;
                }
        }
    }

    // warp butterfly reduce
#pragma unroll
    for (int k = 0; k < 8; k++) {
        float v = s[k];
        v += __shfl_xor_sync(0xffffffffu, v, 16);
        v += __shfl_xor_sync(0xffffffffu, v, 8);
        v += __shfl_xor_sync(0xffffffffu, v, 4);
        v += __shfl_xor_sync(0xffffffffu, v, 2);
        v += __shfl_xor_sync(0xffffffffu, v, 1);
        s[k] = v;
    }
#pragma unroll
    for (int k = 0; k < 70; k++) {
        float v = acc[k];
        v += __shfl_xor_sync(0xffffffffu, v, 16);
        v += __shfl_xor_sync(0xffffffffu, v, 8);
        v += __shfl_xor_sync(0xffffffffu, v, 4);
        v += __shfl_xor_sync(0xffffffffu, v, 2);
        v += __shfl_xor_sync(0xffffffffu, v, 1);
        acc[k] = v;
    }

    __shared__ float red0[2][74];
    __shared__ float red1[2][78];
    int warp = tid >> 5;       // 0..3
    int lane = tid & 31;
    int w2 = warp & 1;
    if (lane == 0) {
        if (half == 0) {
#pragma unroll
            for (int k = 0; k < 8; k++) red0[w2][k] = s[k];
#pragma unroll
            for (int k = 0; k < 66; k++) red0[w2][8 + k] = acc[k];
        } else {
#pragma unroll
            for (int k = 0; k < 8; k++) red1[w2][k] = s[k];
#pragma unroll
            for (int k = 0; k < 70; k++) red1[w2][8 + k] = acc[k];
        }
    }
    __syncthreads();

    if (tid < 74) {
        float a = red0[0][tid] + red0[1][tid];
        int dst = tid < 8 ? tid : 16 + (tid - 8);       // tri rows 0-10 -> [16,82)
        g_part[ng][dst] = a;
    }
    if (tid < 78) {
        float a = red1[0][tid] + red1[1][tid];
        int dst = tid < 8 ? 8 + tid : 82 + (tid - 8);   // tri rows 11-15 -> [82,152)
        g_part[ng][dst] = a;
    }
}

// ------------------------------------------------------------------
// Kernel 1b: reduce batch-whitening sums per group. grid = GROUPS.
// ------------------------------------------------------------------
__global__ __launch_bounds__(256) void bw_kernel() {
    int g = blockIdx.x;
    int t = threadIdx.x;
    if (t < STATS_LEN) {
        float a = 0.f;
#pragma unroll 8
        for (int n = 0; n < N_SAMP; n++)
            a += g_part[n * GROUPS + g][t];
        g_bw[g][t] = a;
    }
}

// ------------------------------------------------------------------
// Kernel 2: mix stats, Newton-Schulz whitening, fold affine.
// grid = NG blocks, 256 threads; thread (i,j) owns element (i,j).
// ------------------------------------------------------------------
__global__ __launch_bounds__(256) void whiten_kernel(
    const float* __restrict__ sw_mean_w,
    const float* __restrict__ sw_var_w,
    const float* __restrict__ weight,
    const float* __restrict__ bias) {

    int ng = blockIdx.x;
    int g = ng & 15;
    int tid = threadIdx.x;
    int i = tid >> 4;
    int j = tid & 15;

    __shared__ float iw[STATS_LEN];
    __shared__ float bw[STATS_LEN];
    __shared__ float cov[CPG][CPG + 1];
    __shared__ float P[CPG][CPG + 1];
    __shared__ float T1[CPG][CPG + 1];
    __shared__ float T2[CPG][CPG + 1];
    __shared__ float meanmix[CPG];

    if (tid < STATS_LEN) {
        iw[tid] = g_part[ng][tid];
        bw[tid] = g_bw[g][tid];
    }
    __syncthreads();

    int a_ = i > j ? i : j;
    int b_ = i > j ? j : i;
    int t = a_ * (a_ + 1) / 2 + b_;

    float sin_ij = iw[16 + t];
    float mi_i = iw[i] * (1.0f / HW);
    float mi_j = iw[j] * (1.0f / HW);
    float sbn = bw[16 + t];
    float mb_i = bw[i] * (1.0f / NHW);
    float mb_j = bw[j] * (1.0f / NHW);

    float cov_in = sin_ij * (1.0f / HW) - mi_i * mi_j;
    float cov_bn = sbn * (1.0f / NHW) - mb_i * mb_j;

    float w0 = sw_mean_w[0], w1 = sw_mean_w[1];
    float mm = fmaxf(w0, w1);
    float e0 = expf(w0 - mm), e1 = expf(w1 - mm);
    float mw0 = e0 / (e0 + e1);
    float mw1 = 1.0f - mw0;

    float v0 = sw_var_w[0], v1 = sw_var_w[1];
    float vm = fmaxf(v0, v1);
    float f0 = expf(v0 - vm), f1 = expf(v1 - vm);
    float vw0 = f0 / (f0 + f1);
    float vw1 = 1.0f - vw0;

    float cval = vw0 * cov_bn + vw1 * cov_in + (i == j ? EPS : 0.0f);
    cov[i][j] = cval;
    if (i == 0) meanmix[j] = mw0 * mb_j + mw1 * mi_j;
    __syncthreads();

    float tr = 0.f;
#pragma unroll
    for (int k = 0; k < CPG; k++) tr += cov[k][k];
    float rTr = 1.0f / tr;
    __syncthreads();   // finish trace reads before overwrite

    cov[i][j] = cval * rTr;          // covN
    P[i][j] = (i == j) ? 1.0f : 0.0f;
    __syncthreads();

    for (int iter = 0; iter < T_ITERS; iter++) {
        float acc = 0.f;
#pragma unroll
        for (int k = 0; k < CPG; k++) acc += P[i][k] * P[k][j];
        T1[i][j] = acc;
        __syncthreads();

        acc = 0.f;
#pragma unroll
        for (int k = 0; k < CPG; k++) acc += T1[i][k] * P[k][j];
        T2[i][j] = acc;
        __syncthreads();

        acc = 0.f;
#pragma unroll
        for (int k = 0; k < CPG; k++) acc += T2[i][k] * cov[k][j];
        float pnew = 1.5f * P[i][j] - 0.5f * acc;
        __syncthreads();
        P[i][j] = pnew;
        __syncthreads();
    }

    float wm_ij = P[i][j] * sqrtf(rTr);
    T1[i][j] = wm_ij;
    float A_ij = weight[g * CPG + i] * wm_ij;
    g_A[ng][i * CPG + j] = A_ij;
    __syncthreads();

    if (tid < CPG) {
        int c = tid;
        float wc = weight[g * CPG + c];
        float acc = 0.f;
#pragma unroll
        for (int d = 0; d < CPG; d++) acc += T1[c][d] * meanmix[d];
        g_b0[ng][c] = bias[g * CPG + c] - wc * acc;
    }
}

// ------------------------------------------------------------------
// Kernel 3: apply  out[c] = sum_d A[c][d]*x[d] + b0[c]   (float4)
// grid = NG * K3_SPLIT blocks, 256 threads, 4 positions/thread.
// (Exact round-2 form: plain loads/stores — .cs hints measured slower.)
// ------------------------------------------------------------------
__global__ __launch_bounds__(256) void apply_kernel(const float* __restrict__ x,
                                                    float* __restrict__ out) {
    int b = blockIdx.x;
    int ng = b >> 2;                 // / K3_SPLIT
    int chunk = b & (K3_SPLIT - 1);
    int n = ng >> 4;
    int g = ng & 15;
    int tid = threadIdx.x;

    __shared__ float sA[CPG][CPG];
    __shared__ float sb[CPG];
    sA[tid >> 4][tid & 15] = g_A[ng][tid];
    if (tid < CPG) sb[tid] = g_b0[ng][tid];
    __syncthreads();

    size_t base = (size_t)(n * C_TOT + g * CPG) * HW
                + (size_t)chunk * K3_POS + (size_t)tid * 4;

    float4 v[CPG];
#pragma unroll
    for (int d = 0; d < CPG; d++)
        v[d] = *(const float4*)(x + base + (size_t)d * HW);

#pragma unroll
    for (int c = 0; c < CPG; c++) {
        float bc = sb[c];
        float4 acc = make_float4(bc, bc, bc, bc);
#pragma unroll
        for (int d = 0; d < CPG; d++) {
            float a = sA[c][d];
            acc.x += a * v[d].x;
            acc.y += a * v[d].y;
            acc.z += a * v[d].z;
            acc.w += a * v[d].w;
        }
        *(float4*)(out + base + (size_t)c * HW) = acc;
    }
}

// ------------------------------------------------------------------
extern "C" void kernel_launch(void* const* d_in, const int* in_sizes, int n_in,
                              void* d_out, int out_size) {
    const float* x      = (const float*)d_in[0];
    const float* sw_m   = (const float*)d_in[1];
    const float* sw_v   = (const float*)d_in[2];
    const float* weight = (const float*)d_in[3];
    const float* bias   = (const float*)d_in[4];
    float* out = (float*)d_out;

    stats_kernel<<<NG, 128>>>(x);
    bw_kernel<<<GROUPS, 256>>>();
    whiten_kernel<<<NG, 256>>>(sw_m, sw_v, weight, bias);
    apply_kernel<<<NG * K3_SPLIT, 256>>>(x, out);
}

// round 7
// speedup vs baseline: 1.6434x; 1.6434x over previous
#include <cuda_runtime.h>
#include <math.h>

#define N_SAMP 32
#define C_TOT 256
#define CPG 16
#define GROUPS 16
#define NG 512
#define HW 4096
#define NHW (N_SAMP * HW)
#define TRI 136
#define STATS_LEN 152          // 16 sums + 136 tri
#define EPS 1e-5f
#define T_ITERS 5

#define K3_SPLIT 4
#define K3_POS (HW / K3_SPLIT)   // 1024

// -------- scratch (device globals) --------
__device__ float g_part[NG][STATS_LEN];   // per-(n,g): [0:16)=sums, [16:152)=tri row-major
__device__ float g_bw[GROUPS][STATS_LEN]; // per-group batch sums
__device__ float g_A[NG][CPG * CPG];
__device__ float g_b0[NG][CPG];

// ------------------------------------------------------------------
// Kernel 1: stats. grid = NG blocks (one per (n,g)), 256 threads.
// 4 quarter-sets of 64 threads (2 warps each):
//   set 0: sums 0-3   + tri rows 0-7   (36 accs)
//   set 1: sums 4-7   + tri rows 8-10  (30 accs)
//   set 2: sums 8-11  + tri rows 11-13 (39 accs)
//   set 3: sums 12-15 + tri rows 14-15 (31 accs)
// Max live ~= 43 accs + 32 (v[16] float2) + addr ~= 85 regs -> no spill.
// Each set loads all 16 channels; L1/L2 absorb the 4x reuse.
// ------------------------------------------------------------------
__global__ __launch_bounds__(256, 2) void stats_kernel(const float* __restrict__ x) {
    int ng = blockIdx.x;
    int n = ng >> 4;
    int g = ng & 15;
    int tid = threadIdx.x;
    int q = tid >> 6;          // set 0..3
    int t = tid & 63;

    const float* __restrict__ xb = x + (size_t)(n * C_TOT + g * CPG) * HW;

    float s[4];
    float acc[43];
#pragma unroll
    for (int i = 0; i < 4; i++) s[i] = 0.f;
#pragma unroll
    for (int i = 0; i < 43; i++) acc[i] = 0.f;

    // 64 threads/set x float2 = 128 positions per pass; 32 passes.
#pragma unroll 2
    for (int pass = 0; pass < HW / 128; pass++) {
        int p = pass * 128 + t * 2;
        float2 v[CPG];
#pragma unroll
        for (int c = 0; c < CPG; c++)
            v[c] = *(const float2*)(xb + (size_t)c * HW + p);

        if (q == 0) {
#pragma unroll
            for (int c = 0; c < 4; c++) s[c] += v[c].x + v[c].y;
            int idx = 0;
#pragma unroll
            for (int i = 0; i < 8; i++)
#pragma unroll
                for (int j = 0; j <= i; j++) {
                    acc[idx] += v[i].x * v[j].x + v[i].y * v[j].y;
                    idx++;
                }
        } else if (q == 1) {
#pragma unroll
            for (int c = 0; c < 4; c++) s[c] += v[c + 4].x + v[c + 4].y;
            int idx = 0;
#pragma unroll
            for (int i = 8; i < 11; i++)
#pragma unroll
                for (int j = 0; j <= i; j++) {
                    acc[idx] += v[i].x * v[j].x + v[i].y * v[j].y;
                    idx++;
                }
        } else if (q == 2) {
#pragma unroll
            for (int c = 0; c < 4; c++) s[c] += v[c + 8].x + v[c + 8].y;
            int idx = 0;
#pragma unroll
            for (int i = 11; i < 14; i++)
#pragma unroll
                for (int j = 0; j <= i; j++) {
                    acc[idx] += v[i].x * v[j].x + v[i].y * v[j].y;
                    idx++;
                }
        } else {
#pragma unroll
            for (int c = 0; c < 4; c++) s[c] += v[c + 12].x + v[c + 12].y;
            int idx = 0;
#pragma unroll
            for (int i = 14; i < 16; i++)
#pragma unroll
                for (int j = 0; j <= i; j++) {
                    acc[idx] += v[i].x * v[j].x + v[i].y * v[j].y;
                    idx++;
                }
        }
    }

    // warp butterfly reduce (4 sums + up to 43 accs)
#pragma unroll
    for (int k = 0; k < 4; k++) {
        float v = s[k];
        v += __shfl_xor_sync(0xffffffffu, v, 16);
        v += __shfl_xor_sync(0xffffffffu, v, 8);
        v += __shfl_xor_sync(0xffffffffu, v, 4);
        v += __shfl_xor_sync(0xffffffffu, v, 2);
        v += __shfl_xor_sync(0xffffffffu, v, 1);
        s[k] = v;
    }
#pragma unroll
    for (int k = 0; k < 43; k++) {
        float v = acc[k];
        v += __shfl_xor_sync(0xffffffffu, v, 16);
        v += __shfl_xor_sync(0xffffffffu, v, 8);
        v += __shfl_xor_sync(0xffffffffu, v, 4);
        v += __shfl_xor_sync(0xffffffffu, v, 2);
        v += __shfl_xor_sync(0xffffffffu, v, 1);
        acc[k] = v;
    }

    __shared__ float red[4][2][47];
    int warp = tid >> 5;
    int lane = tid & 31;
    int w2 = warp & 1;
    if (lane == 0) {
#pragma unroll
        for (int k = 0; k < 4; k++) red[q][w2][k] = s[k];
#pragma unroll
        for (int k = 0; k < 43; k++) red[q][w2][4 + k] = acc[k];
    }
    __syncthreads();

    // 152 outputs: set lengths 40 / 34 / 43 / 35
    if (tid < 152) {
        int set, loc;
        if (tid < 40)       { set = 0; loc = tid; }
        else if (tid < 74)  { set = 1; loc = tid - 40; }
        else if (tid < 117) { set = 2; loc = tid - 74; }
        else                { set = 3; loc = tid - 117; }
        float a = red[set][0][loc] + red[set][1][loc];
        int dst;
        if (loc < 4) dst = set * 4 + loc;                 // channel sums
        else {
            const int triBase[4] = {16, 52, 82, 121};     // 16 + {0,36,66,105}
            dst = triBase[set] + (loc - 4);
        }
        g_part[ng][dst] = a;
    }
}

// ------------------------------------------------------------------
// Kernel 1b: reduce batch-whitening sums per group. grid = GROUPS.
// ------------------------------------------------------------------
__global__ __launch_bounds__(256) void bw_kernel() {
    int g = blockIdx.x;
    int t = threadIdx.x;
    if (t < STATS_LEN) {
        float a = 0.f;
#pragma unroll 8
        for (int n = 0; n < N_SAMP; n++)
            a += g_part[n * GROUPS + g][t];
        g_bw[g][t] = a;
    }
}

// ------------------------------------------------------------------
// Kernel 2: mix stats, Newton-Schulz whitening, fold affine.
// grid = NG blocks, 256 threads; thread (i,j) owns element (i,j).
// ------------------------------------------------------------------
__global__ __launch_bounds__(256) void whiten_kernel(
    const float* __restrict__ sw_mean_w,
    const float* __restrict__ sw_var_w,
    const float* __restrict__ weight,
    const float* __restrict__ bias) {

    int ng = blockIdx.x;
    int g = ng & 15;
    int tid = threadIdx.x;
    int i = tid >> 4;
    int j = tid & 15;

    __shared__ float iw[STATS_LEN];
    __shared__ float bw[STATS_LEN];
    __shared__ float cov[CPG][CPG + 1];
    __shared__ float P[CPG][CPG + 1];
    __shared__ float T1[CPG][CPG + 1];
    __shared__ float T2[CPG][CPG + 1];
    __shared__ float meanmix[CPG];

    if (tid < STATS_LEN) {
        iw[tid] = g_part[ng][tid];
        bw[tid] = g_bw[g][tid];
    }
    __syncthreads();

    int a_ = i > j ? i : j;
    int b_ = i > j ? j : i;
    int t = a_ * (a_ + 1) / 2 + b_;

    float sin_ij = iw[16 + t];
    float mi_i = iw[i] * (1.0f / HW);
    float mi_j = iw[j] * (1.0f / HW);
    float sbn = bw[16 + t];
    float mb_i = bw[i] * (1.0f / NHW);
    float mb_j = bw[j] * (1.0f / NHW);

    float cov_in = sin_ij * (1.0f / HW) - mi_i * mi_j;
    float cov_bn = sbn * (1.0f / NHW) - mb_i * mb_j;

    float w0 = sw_mean_w[0], w1 = sw_mean_w[1];
    float mm = fmaxf(w0, w1);
    float e0 = expf(w0 - mm), e1 = expf(w1 - mm);
    float mw0 = e0 / (e0 + e1);
    float mw1 = 1.0f - mw0;

    float v0 = sw_var_w[0], v1 = sw_var_w[1];
    float vm = fmaxf(v0, v1);
    float f0 = expf(v0 - vm), f1 = expf(v1 - vm);
    float vw0 = f0 / (f0 + f1);
    float vw1 = 1.0f - vw0;

    float cval = vw0 * cov_bn + vw1 * cov_in + (i == j ? EPS : 0.0f);
    cov[i][j] = cval;
    if (i == 0) meanmix[j] = mw0 * mb_j + mw1 * mi_j;
    __syncthreads();

    float tr = 0.f;
#pragma unroll
    for (int k = 0; k < CPG; k++) tr += cov[k][k];
    float rTr = 1.0f / tr;
    __syncthreads();   // finish trace reads before overwrite

    cov[i][j] = cval * rTr;          // covN
    P[i][j] = (i == j) ? 1.0f : 0.0f;
    __syncthreads();

    for (int iter = 0; iter < T_ITERS; iter++) {
        float acc = 0.f;
#pragma unroll
        for (int k = 0; k < CPG; k++) acc += P[i][k] * P[k][j];
        T1[i][j] = acc;
        __syncthreads();

        acc = 0.f;
#pragma unroll
        for (int k = 0; k < CPG; k++) acc += T1[i][k] * P[k][j];
        T2[i][j] = acc;
        __syncthreads();

        acc = 0.f;
#pragma unroll
        for (int k = 0; k < CPG; k++) acc += T2[i][k] * cov[k][j];
        float pnew = 1.5f * P[i][j] - 0.5f * acc;
        __syncthreads();
        P[i][j] = pnew;
        __syncthreads();
    }

    float wm_ij = P[i][j] * sqrtf(rTr);
    T1[i][j] = wm_ij;
    float A_ij = weight[g * CPG + i] * wm_ij;
    g_A[ng][i * CPG + j] = A_ij;
    __syncthreads();

    if (tid < CPG) {
        int c = tid;
        float wc = weight[g * CPG + c];
        float acc = 0.f;
#pragma unroll
        for (int d = 0; d < CPG; d++) acc += T1[c][d] * meanmix[d];
        g_b0[ng][c] = bias[g * CPG + c] - wc * acc;
    }
}

// ------------------------------------------------------------------
// Kernel 3: apply  out[c] = sum_d A[c][d]*x[d] + b0[c]   (float4)
// grid = NG * K3_SPLIT blocks, 256 threads, 4 positions/thread.
// ------------------------------------------------------------------
__global__ __launch_bounds__(256) void apply_kernel(const float* __restrict__ x,
                                                    float* __restrict__ out) {
    int b = blockIdx.x;
    int ng = b >> 2;                 // / K3_SPLIT
    int chunk = b & (K3_SPLIT - 1);
    int n = ng >> 4;
    int g = ng & 15;
    int tid = threadIdx.x;

    __shared__ float sA[CPG][CPG];
    __shared__ float sb[CPG];
    sA[tid >> 4][tid & 15] = g_A[ng][tid];
    if (tid < CPG) sb[tid] = g_b0[ng][tid];
    __syncthreads();

    size_t base = (size_t)(n * C_TOT + g * CPG) * HW
                + (size_t)chunk * K3_POS + (size_t)tid * 4;

    float4 v[CPG];
#pragma unroll
    for (int d = 0; d < CPG; d++)
        v[d] = *(const float4*)(x + base + (size_t)d * HW);

#pragma unroll
    for (int c = 0; c < CPG; c++) {
        float bc = sb[c];
        float4 acc = make_float4(bc, bc, bc, bc);
#pragma unroll
        for (int d = 0; d < CPG; d++) {
            float a = sA[c][d];
            acc.x += a * v[d].x;
            acc.y += a * v[d].y;
            acc.z += a * v[d].z;
            acc.w += a * v[d].w;
        }
        *(float4*)(out + base + (size_t)c * HW) = acc;
    }
}

// ------------------------------------------------------------------
extern "C" void kernel_launch(void* const* d_in, const int* in_sizes, int n_in,
                              void* d_out, int out_size) {
    const float* x      = (const float*)d_in[0];
    const float* sw_m   = (const float*)d_in[1];
    const float* sw_v   = (const float*)d_in[2];
    const float* weight = (const float*)d_in[3];
    const float* bias   = (const float*)d_in[4];
    float* out = (float*)d_out;

    stats_kernel<<<NG, 256>>>(x);
    bw_kernel<<<GROUPS, 256>>>();
    whiten_kernel<<<NG, 256>>>(sw_m, sw_v, weight, bias);
    apply_kernel<<<NG * K3_SPLIT, 256>>>(x, out);
}

// round 8
// speedup vs baseline: 1.7408x; 1.0593x over previous
#include <cuda_runtime.h>
#include <math.h>

#define N_SAMP 32
#define C_TOT 256
#define CPG 16
#define GROUPS 16
#define NG 512
#define HW 4096
#define NHW (N_SAMP * HW)
#define TRI 136
#define STATS_LEN 152          // 16 sums + 136 tri
#define EPS 1e-5f
#define T_ITERS 5

#define K3_SPLIT 4
#define K3_POS (HW / K3_SPLIT)   // 1024

// -------- scratch (device globals) --------
__device__ float g_part[NG][STATS_LEN];   // per-(n,g): [0:16)=sums, [16:152)=tri row-major
__device__ float g_A[NG][CPG * CPG];
__device__ float g_b0[NG][CPG];

// ------------------------------------------------------------------
// Kernel 1: stats. grid = NG blocks (one per (n,g)), 256 threads.
// 4 quarter-sets of 64 threads (2 warps each). Each set loads ONLY the
// channels its triangle rows need:
//   set 0: ch 0-7  : sums 0-3   + tri rows 0-7   (36 accs)
//   set 1: ch 0-10 : sums 4-7   + tri rows 8-10  (30 accs)
//   set 2: ch 0-13 : sums 8-11  + tri rows 11-13 (39 accs)
//   set 3: ch 0-15 : sums 12-15 + tri rows 14-15 (31 accs)
// Worst live set ~= 43 accs + 28 v-regs + addr ~= 85 regs. No unroll of
// the pass loop (loads within a pass give MLP 11-16 already).
// ------------------------------------------------------------------
__global__ __launch_bounds__(256, 2) void stats_kernel(const float* __restrict__ x) {
    int ng = blockIdx.x;
    int n = ng >> 4;
    int g = ng & 15;
    int tid = threadIdx.x;
    int q = tid >> 6;          // set 0..3
    int t = tid & 63;

    const float* __restrict__ xb = x + (size_t)(n * C_TOT + g * CPG) * HW;

    float s[4];
    float acc[43];
#pragma unroll
    for (int i = 0; i < 4; i++) s[i] = 0.f;
#pragma unroll
    for (int i = 0; i < 43; i++) acc[i] = 0.f;

    // 64 threads/set x float2 = 128 positions per pass; 32 passes.
    if (q == 0) {
#pragma unroll 1
        for (int pass = 0; pass < HW / 128; pass++) {
            int p = pass * 128 + t * 2;
            float2 v[8];
#pragma unroll
            for (int c = 0; c < 8; c++)
                v[c] = *(const float2*)(xb + (size_t)c * HW + p);
#pragma unroll
            for (int c = 0; c < 4; c++) s[c] += v[c].x + v[c].y;
            int idx = 0;
#pragma unroll
            for (int i = 0; i < 8; i++)
#pragma unroll
                for (int j = 0; j <= i; j++) {
                    acc[idx] += v[i].x * v[j].x + v[i].y * v[j].y;
                    idx++;
                }
        }
    } else if (q == 1) {
#pragma unroll 1
        for (int pass = 0; pass < HW / 128; pass++) {
            int p = pass * 128 + t * 2;
            float2 v[11];
#pragma unroll
            for (int c = 0; c < 11; c++)
                v[c] = *(const float2*)(xb + (size_t)c * HW + p);
#pragma unroll
            for (int c = 0; c < 4; c++) s[c] += v[c + 4].x + v[c + 4].y;
            int idx = 0;
#pragma unroll
            for (int i = 8; i < 11; i++)
#pragma unroll
                for (int j = 0; j <= i; j++) {
                    acc[idx] += v[i].x * v[j].x + v[i].y * v[j].y;
                    idx++;
                }
        }
    } else if (q == 2) {
#pragma unroll 1
        for (int pass = 0; pass < HW / 128; pass++) {
            int p = pass * 128 + t * 2;
            float2 v[14];
#pragma unroll
            for (int c = 0; c < 14; c++)
                v[c] = *(const float2*)(xb + (size_t)c * HW + p);
#pragma unroll
            for (int c = 0; c < 4; c++) s[c] += v[c + 8].x + v[c + 8].y;
            int idx = 0;
#pragma unroll
            for (int i = 11; i < 14; i++)
#pragma unroll
                for (int j = 0; j <= i; j++) {
                    acc[idx] += v[i].x * v[j].x + v[i].y * v[j].y;
                    idx++;
                }
        }
    } else {
#pragma unroll 1
        for (int pass = 0; pass < HW / 128; pass++) {
            int p = pass * 128 + t * 2;
            float2 v[16];
#pragma unroll
            for (int c = 0; c < 16; c++)
                v[c] = *(const float2*)(xb + (size_t)c * HW + p);
#pragma unroll
            for (int c = 0; c < 4; c++) s[c] += v[c + 12].x + v[c + 12].y;
            int idx = 0;
#pragma unroll
            for (int i = 14; i < 16; i++)
#pragma unroll
                for (int j = 0; j <= i; j++) {
                    acc[idx] += v[i].x * v[j].x + v[i].y * v[j].y;
                    idx++;
                }
        }
    }

    // warp butterfly reduce (4 sums + up to 43 accs)
#pragma unroll
    for (int k = 0; k < 4; k++) {
        float v = s[k];
        v += __shfl_xor_sync(0xffffffffu, v, 16);
        v += __shfl_xor_sync(0xffffffffu, v, 8);
        v += __shfl_xor_sync(0xffffffffu, v, 4);
        v += __shfl_xor_sync(0xffffffffu, v, 2);
        v += __shfl_xor_sync(0xffffffffu, v, 1);
        s[k] = v;
    }
#pragma unroll
    for (int k = 0; k < 43; k++) {
        float v = acc[k];
        v += __shfl_xor_sync(0xffffffffu, v, 16);
        v += __shfl_xor_sync(0xffffffffu, v, 8);
        v += __shfl_xor_sync(0xffffffffu, v, 4);
        v += __shfl_xor_sync(0xffffffffu, v, 2);
        v += __shfl_xor_sync(0xffffffffu, v, 1);
        acc[k] = v;
    }

    __shared__ float red[4][2][47];
    int warp = tid >> 5;
    int lane = tid & 31;
    int w2 = warp & 1;
    if (lane == 0) {
#pragma unroll
        for (int k = 0; k < 4; k++) red[q][w2][k] = s[k];
#pragma unroll
        for (int k = 0; k < 43; k++) red[q][w2][4 + k] = acc[k];
    }
    __syncthreads();

    // 152 outputs: set lengths 40 / 34 / 43 / 35
    if (tid < 152) {
        int set, loc;
        if (tid < 40)       { set = 0; loc = tid; }
        else if (tid < 74)  { set = 1; loc = tid - 40; }
        else if (tid < 117) { set = 2; loc = tid - 74; }
        else                { set = 3; loc = tid - 117; }
        float a = red[set][0][loc] + red[set][1][loc];
        int dst;
        if (loc < 4) dst = set * 4 + loc;                 // channel sums
        else {
            const int triBase[4] = {16, 52, 82, 121};     // 16 + {0,36,66,105}
            dst = triBase[set] + (loc - 4);
        }
        g_part[ng][dst] = a;
    }
}

// ------------------------------------------------------------------
// Kernel 2: mix stats (BW sums computed inline), Newton-Schulz, fold.
// grid = NG blocks, 256 threads; thread (i,j) owns element (i,j).
// ------------------------------------------------------------------
__global__ __launch_bounds__(256) void whiten_kernel(
    const float* __restrict__ sw_mean_w,
    const float* __restrict__ sw_var_w,
    const float* __restrict__ weight,
    const float* __restrict__ bias) {

    int ng = blockIdx.x;
    int g = ng & 15;
    int tid = threadIdx.x;
    int i = tid >> 4;
    int j = tid & 15;

    __shared__ float iw[STATS_LEN];
    __shared__ float bw[STATS_LEN];
    __shared__ float cov[CPG][CPG + 1];
    __shared__ float P[CPG][CPG + 1];
    __shared__ float T1[CPG][CPG + 1];
    __shared__ float T2[CPG][CPG + 1];
    __shared__ float meanmix[CPG];

    if (tid < STATS_LEN) {
        iw[tid] = g_part[ng][tid];
        float a = 0.f;
#pragma unroll 8
        for (int n2 = 0; n2 < N_SAMP; n2++)
            a += g_part[n2 * GROUPS + g][tid];
        bw[tid] = a;
    }
    __syncthreads();

    int a_ = i > j ? i : j;
    int b_ = i > j ? j : i;
    int t = a_ * (a_ + 1) / 2 + b_;

    float sin_ij = iw[16 + t];
    float mi_i = iw[i] * (1.0f / HW);
    float mi_j = iw[j] * (1.0f / HW);
    float sbn = bw[16 + t];
    float mb_i = bw[i] * (1.0f / NHW);
    float mb_j = bw[j] * (1.0f / NHW);

    float cov_in = sin_ij * (1.0f / HW) - mi_i * mi_j;
    float cov_bn = sbn * (1.0f / NHW) - mb_i * mb_j;

    float w0 = sw_mean_w[0], w1 = sw_mean_w[1];
    float mm = fmaxf(w0, w1);
    float e0 = expf(w0 - mm), e1 = expf(w1 - mm);
    float mw0 = e0 / (e0 + e1);
    float mw1 = 1.0f - mw0;

    float v0 = sw_var_w[0], v1 = sw_var_w[1];
    float vm = fmaxf(v0, v1);
    float f0 = expf(v0 - vm), f1 = expf(v1 - vm);
    float vw0 = f0 / (f0 + f1);
    float vw1 = 1.0f - vw0;

    float cval = vw0 * cov_bn + vw1 * cov_in + (i == j ? EPS : 0.0f);
    cov[i][j] = cval;
    if (i == 0) meanmix[j] = mw0 * mb_j + mw1 * mi_j;
    __syncthreads();

    float tr = 0.f;
#pragma unroll
    for (int k = 0; k < CPG; k++) tr += cov[k][k];
    float rTr = 1.0f / tr;
    __syncthreads();   // finish trace reads before overwrite

    cov[i][j] = cval * rTr;          // covN
    P[i][j] = (i == j) ? 1.0f : 0.0f;
    __syncthreads();

    for (int iter = 0; iter < T_ITERS; iter++) {
        float acc = 0.f;
#pragma unroll
        for (int k = 0; k < CPG; k++) acc += P[i][k] * P[k][j];
        T1[i][j] = acc;
        __syncthreads();

        acc = 0.f;
#pragma unroll
        for (int k = 0; k < CPG; k++) acc += T1[i][k] * P[k][j];
        T2[i][j] = acc;
        __syncthreads();

        acc = 0.f;
#pragma unroll
        for (int k = 0; k < CPG; k++) acc += T2[i][k] * cov[k][j];
        float pnew = 1.5f * P[i][j] - 0.5f * acc;
        __syncthreads();
        P[i][j] = pnew;
        __syncthreads();
    }

    float wm_ij = P[i][j] * sqrtf(rTr);
    T1[i][j] = wm_ij;
    float A_ij = weight[g * CPG + i] * wm_ij;
    g_A[ng][i * CPG + j] = A_ij;
    __syncthreads();

    if (tid < CPG) {
        int c = tid;
        float wc = weight[g * CPG + c];
        float acc = 0.f;
#pragma unroll
        for (int d = 0; d < CPG; d++) acc += T1[c][d] * meanmix[d];
        g_b0[ng][c] = bias[g * CPG + c] - wc * acc;
    }
}

// ------------------------------------------------------------------
// Kernel 3: apply  out[c] = sum_d A[c][d]*x[d] + b0[c]   (float4)
// grid = NG * K3_SPLIT blocks, 256 threads, 4 positions/thread.
// ------------------------------------------------------------------
__global__ __launch_bounds__(256) void apply_kernel(const float* __restrict__ x,
                                                    float* __restrict__ out) {
    int b = blockIdx.x;
    int ng = b >> 2;                 // / K3_SPLIT
    int chunk = b & (K3_SPLIT - 1);
    int n = ng >> 4;
    int g = ng & 15;
    int tid = threadIdx.x;

    __shared__ float sA[CPG][CPG];
    __shared__ float sb[CPG];
    sA[tid >> 4][tid & 15] = g_A[ng][tid];
    if (tid < CPG) sb[tid] = g_b0[ng][tid];
    __syncthreads();

    size_t base = (size_t)(n * C_TOT + g * CPG) * HW
                + (size_t)chunk * K3_POS + (size_t)tid * 4;

    float4 v[CPG];
#pragma unroll
    for (int d = 0; d < CPG; d++)
        v[d] = *(const float4*)(x + base + (size_t)d * HW);

#pragma unroll
    for (int c = 0; c < CPG; c++) {
        float bc = sb[c];
        float4 acc = make_float4(bc, bc, bc, bc);
#pragma unroll
        for (int d = 0; d < CPG; d++) {
            float a = sA[c][d];
            acc.x += a * v[d].x;
            acc.y += a * v[d].y;
            acc.z += a * v[d].z;
            acc.w += a * v[d].w;
        }
        *(float4*)(out + base + (size_t)c * HW) = acc;
    }
}

// ------------------------------------------------------------------
extern "C" void kernel_launch(void* const* d_in, const int* in_sizes, int n_in,
                              void* d_out, int out_size) {
    const float* x      = (const float*)d_in[0];
    const float* sw_m   = (const float*)d_in[1];
    const float* sw_v   = (const float*)d_in[2];
    const float* weight = (const float*)d_in[3];
    const float* bias   = (const float*)d_in[4];
    float* out = (float*)d_out;

    stats_kernel<<<NG, 256>>>(x);
    whiten_kernel<<<NG, 256>>>(sw_m, sw_v, weight, bias);
    apply_kernel<<<NG * K3_SPLIT, 256>>>(x, out);
}

// round 9
// speedup vs baseline: 1.9993x; 1.1485x over previous
#include <cuda_runtime.h>
#include <math.h>

#define N_SAMP 32
#define C_TOT 256
#define CPG 16
#define GROUPS 16
#define NG 512
#define HW 4096
#define NHW (N_SAMP * HW)
#define TRI 136
#define STATS_LEN 152          // 16 sums + 136 tri
#define EPS 1e-5f
#define T_ITERS 5

#define K3_SPLIT 4
#define K3_POS (HW / K3_SPLIT)   // 1024

// -------- scratch (device globals) --------
__device__ float g_part[NG][STATS_LEN];   // per-(n,g): [0:16)=sums, [16:152)=tri row-major
__device__ float g_A[NG][CPG * CPG];
__device__ float g_b0[NG][CPG];

// ------------------------------------------------------------------
// Kernel 1: stats. grid = NG blocks (one per (n,g)), 256 threads.
// 4 quarter-sets of 64 threads (2 warps each). Each set loads ONLY the
// channels its triangle rows need, as float4 (4 positions/thread/pass):
//   set 0: ch 0-7  : sums 0-3   + tri rows 0-7   (36 accs)
//   set 1: ch 0-10 : sums 4-7   + tri rows 8-10  (30 accs)
//   set 2: ch 0-13 : sums 8-11  + tri rows 11-13 (39 accs)
//   set 3: ch 0-15 : sums 12-15 + tri rows 14-15 (31 accs)
// Worst live ~= 43 acc + 64 v + addr ~= 110 regs (<128 cap, no spill).
// float4 doubles FMA-per-load-roundtrip vs float2 -> latency hidden.
// ------------------------------------------------------------------
__global__ __launch_bounds__(256, 2) void stats_kernel(const float* __restrict__ x) {
    int ng = blockIdx.x;
    int n = ng >> 4;
    int g = ng & 15;
    int tid = threadIdx.x;
    int q = tid >> 6;          // set 0..3
    int t = tid & 63;

    const float* __restrict__ xb = x + (size_t)(n * C_TOT + g * CPG) * HW;

    float s[4];
    float acc[43];
#pragma unroll
    for (int i = 0; i < 4; i++) s[i] = 0.f;
#pragma unroll
    for (int i = 0; i < 43; i++) acc[i] = 0.f;

    // 64 threads/set x float4 = 256 positions per pass; 16 passes.
    if (q == 0) {
#pragma unroll 1
        for (int pass = 0; pass < HW / 256; pass++) {
            int p = pass * 256 + t * 4;
            float4 v[8];
#pragma unroll
            for (int c = 0; c < 8; c++)
                v[c] = *(const float4*)(xb + (size_t)c * HW + p);
#pragma unroll
            for (int c = 0; c < 4; c++) s[c] += (v[c].x + v[c].y) + (v[c].z + v[c].w);
            int idx = 0;
#pragma unroll
            for (int i = 0; i < 8; i++)
#pragma unroll
                for (int j = 0; j <= i; j++) {
                    acc[idx] += v[i].x * v[j].x + v[i].y * v[j].y
                              + v[i].z * v[j].z + v[i].w * v[j].w;
                    idx++;
                }
        }
    } else if (q == 1) {
#pragma unroll 1
        for (int pass = 0; pass < HW / 256; pass++) {
            int p = pass * 256 + t * 4;
            float4 v[11];
#pragma unroll
            for (int c = 0; c < 11; c++)
                v[c] = *(const float4*)(xb + (size_t)c * HW + p);
#pragma unroll
            for (int c = 0; c < 4; c++) s[c] += (v[c + 4].x + v[c + 4].y) + (v[c + 4].z + v[c + 4].w);
            int idx = 0;
#pragma unroll
            for (int i = 8; i < 11; i++)
#pragma unroll
                for (int j = 0; j <= i; j++) {
                    acc[idx] += v[i].x * v[j].x + v[i].y * v[j].y
                              + v[i].z * v[j].z + v[i].w * v[j].w;
                    idx++;
                }
        }
    } else if (q == 2) {
#pragma unroll 1
        for (int pass = 0; pass < HW / 256; pass++) {
            int p = pass * 256 + t * 4;
            float4 v[14];
#pragma unroll
            for (int c = 0; c < 14; c++)
                v[c] = *(const float4*)(xb + (size_t)c * HW + p);
#pragma unroll
            for (int c = 0; c < 4; c++) s[c] += (v[c + 8].x + v[c + 8].y) + (v[c + 8].z + v[c + 8].w);
            int idx = 0;
#pragma unroll
            for (int i = 11; i < 14; i++)
#pragma unroll
                for (int j = 0; j <= i; j++) {
                    acc[idx] += v[i].x * v[j].x + v[i].y * v[j].y
                              + v[i].z * v[j].z + v[i].w * v[j].w;
                    idx++;
                }
        }
    } else {
#pragma unroll 1
        for (int pass = 0; pass < HW / 256; pass++) {
            int p = pass * 256 + t * 4;
            float4 v[16];
#pragma unroll
            for (int c = 0; c < 16; c++)
                v[c] = *(const float4*)(xb + (size_t)c * HW + p);
#pragma unroll
            for (int c = 0; c < 4; c++) s[c] += (v[c + 12].x + v[c + 12].y) + (v[c + 12].z + v[c + 12].w);
            int idx = 0;
#pragma unroll
            for (int i = 14; i < 16; i++)
#pragma unroll
                for (int j = 0; j <= i; j++) {
                    acc[idx] += v[i].x * v[j].x + v[i].y * v[j].y
                              + v[i].z * v[j].z + v[i].w * v[j].w;
                    idx++;
                }
        }
    }

    // warp butterfly reduce (4 sums + up to 43 accs)
#pragma unroll
    for (int k = 0; k < 4; k++) {
        float v = s[k];
        v += __shfl_xor_sync(0xffffffffu, v, 16);
        v += __shfl_xor_sync(0xffffffffu, v, 8);
        v += __shfl_xor_sync(0xffffffffu, v, 4);
        v += __shfl_xor_sync(0xffffffffu, v, 2);
        v += __shfl_xor_sync(0xffffffffu, v, 1);
        s[k] = v;
    }
#pragma unroll
    for (int k = 0; k < 43; k++) {
        float v = acc[k];
        v += __shfl_xor_sync(0xffffffffu, v, 16);
        v += __shfl_xor_sync(0xffffffffu, v, 8);
        v += __shfl_xor_sync(0xffffffffu, v, 4);
        v += __shfl_xor_sync(0xffffffffu, v, 2);
        v += __shfl_xor_sync(0xffffffffu, v, 1);
        acc[k] = v;
    }

    __shared__ float red[4][2][47];
    int warp = tid >> 5;
    int lane = tid & 31;
    int w2 = warp & 1;
    if (lane == 0) {
#pragma unroll
        for (int k = 0; k < 4; k++) red[q][w2][k] = s[k];
#pragma unroll
        for (int k = 0; k < 43; k++) red[q][w2][4 + k] = acc[k];
    }
    __syncthreads();

    // 152 outputs: set lengths 40 / 34 / 43 / 35
    if (tid < 152) {
        int set, loc;
        if (tid < 40)       { set = 0; loc = tid; }
        else if (tid < 74)  { set = 1; loc = tid - 40; }
        else if (tid < 117) { set = 2; loc = tid - 74; }
        else                { set = 3; loc = tid - 117; }
        float a = red[set][0][loc] + red[set][1][loc];
        int dst;
        if (loc < 4) dst = set * 4 + loc;                 // channel sums
        else {
            const int triBase[4] = {16, 52, 82, 121};     // 16 + {0,36,66,105}
            dst = triBase[set] + (loc - 4);
        }
        g_part[ng][dst] = a;
    }
}

// ------------------------------------------------------------------
// Kernel 2: mix stats (BW sums computed inline), Newton-Schulz, fold.
// grid = NG blocks, 256 threads; thread (i,j) owns element (i,j).
// ------------------------------------------------------------------
__global__ __launch_bounds__(256) void whiten_kernel(
    const float* __restrict__ sw_mean_w,
    const float* __restrict__ sw_var_w,
    const float* __restrict__ weight,
    const float* __restrict__ bias) {

    int ng = blockIdx.x;
    int g = ng & 15;
    int tid = threadIdx.x;
    int i = tid >> 4;
    int j = tid & 15;

    __shared__ float iw[STATS_LEN];
    __shared__ float bw[STATS_LEN];
    __shared__ float cov[CPG][CPG + 1];
    __shared__ float P[CPG][CPG + 1];
    __shared__ float T1[CPG][CPG + 1];
    __shared__ float T2[CPG][CPG + 1];
    __shared__ float meanmix[CPG];

    if (tid < STATS_LEN) {
        iw[tid] = g_part[ng][tid];
        float a = 0.f;
#pragma unroll 8
        for (int n2 = 0; n2 < N_SAMP; n2++)
            a += g_part[n2 * GROUPS + g][tid];
        bw[tid] = a;
    }
    __syncthreads();

    int a_ = i > j ? i : j;
    int b_ = i > j ? j : i;
    int t = a_ * (a_ + 1) / 2 + b_;

    float sin_ij = iw[16 + t];
    float mi_i = iw[i] * (1.0f / HW);
    float mi_j = iw[j] * (1.0f / HW);
    float sbn = bw[16 + t];
    float mb_i = bw[i] * (1.0f / NHW);
    float mb_j = bw[j] * (1.0f / NHW);

    float cov_in = sin_ij * (1.0f / HW) - mi_i * mi_j;
    float cov_bn = sbn * (1.0f / NHW) - mb_i * mb_j;

    float w0 = sw_mean_w[0], w1 = sw_mean_w[1];
    float mm = fmaxf(w0, w1);
    float e0 = expf(w0 - mm), e1 = expf(w1 - mm);
    float mw0 = e0 / (e0 + e1);
    float mw1 = 1.0f - mw0;

    float v0 = sw_var_w[0], v1 = sw_var_w[1];
    float vm = fmaxf(v0, v1);
    float f0 = expf(v0 - vm), f1 = expf(v1 - vm);
    float vw0 = f0 / (f0 + f1);
    float vw1 = 1.0f - vw0;

    float cval = vw0 * cov_bn + vw1 * cov_in + (i == j ? EPS : 0.0f);
    cov[i][j] = cval;
    if (i == 0) meanmix[j] = mw0 * mb_j + mw1 * mi_j;
    __syncthreads();

    float tr = 0.f;
#pragma unroll
    for (int k = 0; k < CPG; k++) tr += cov[k][k];
    float rTr = 1.0f / tr;
    __syncthreads();   // finish trace reads before overwrite

    cov[i][j] = cval * rTr;          // covN
    P[i][j] = (i == j) ? 1.0f : 0.0f;
    __syncthreads();

    for (int iter = 0; iter < T_ITERS; iter++) {
        float acc = 0.f;
#pragma unroll
        for (int k = 0; k < CPG; k++) acc += P[i][k] * P[k][j];
        T1[i][j] = acc;
        __syncthreads();

        acc = 0.f;
#pragma unroll
        for (int k = 0; k < CPG; k++) acc += T1[i][k] * P[k][j];
        T2[i][j] = acc;
        __syncthreads();

        acc = 0.f;
#pragma unroll
        for (int k = 0; k < CPG; k++) acc += T2[i][k] * cov[k][j];
        float pnew = 1.5f * P[i][j] - 0.5f * acc;
        __syncthreads();
        P[i][j] = pnew;
        __syncthreads();
    }

    float wm_ij = P[i][j] * sqrtf(rTr);
    T1[i][j] = wm_ij;
    float A_ij = weight[g * CPG + i] * wm_ij;
    g_A[ng][i * CPG + j] = A_ij;
    __syncthreads();

    if (tid < CPG) {
        int c = tid;
        float wc = weight[g * CPG + c];
        float acc = 0.f;
#pragma unroll
        for (int d = 0; d < CPG; d++) acc += T1[c][d] * meanmix[d];
        g_b0[ng][c] = bias[g * CPG + c] - wc * acc;
    }
}

// ------------------------------------------------------------------
// Kernel 3: apply  out[c] = sum_d A[c][d]*x[d] + b0[c]   (float4)
// grid = NG * K3_SPLIT blocks, 256 threads, 4 positions/thread.
// ------------------------------------------------------------------
__global__ __launch_bounds__(256) void apply_kernel(const float* __restrict__ x,
                                                    float* __restrict__ out) {
    int b = blockIdx.x;
    int ng = b >> 2;                 // / K3_SPLIT
    int chunk = b & (K3_SPLIT - 1);
    int n = ng >> 4;
    int g = ng & 15;
    int tid = threadIdx.x;

    __shared__ float sA[CPG][CPG];
    __shared__ float sb[CPG];
    sA[tid >> 4][tid & 15] = g_A[ng][tid];
    if (tid < CPG) sb[tid] = g_b0[ng][tid];
    __syncthreads();

    size_t base = (size_t)(n * C_TOT + g * CPG) * HW
                + (size_t)chunk * K3_POS + (size_t)tid * 4;

    float4 v[CPG];
#pragma unroll
    for (int d = 0; d < CPG; d++)
        v[d] = *(const float4*)(x + base + (size_t)d * HW);

#pragma unroll
    for (int c = 0; c < CPG; c++) {
        float bc = sb[c];
        float4 acc = make_float4(bc, bc, bc, bc);
#pragma unroll
        for (int d = 0; d < CPG; d++) {
            float a = sA[c][d];
            acc.x += a * v[d].x;
            acc.y += a * v[d].y;
            acc.z += a * v[d].z;
            acc.w += a * v[d].w;
        }
        *(float4*)(out + base + (size_t)c * HW) = acc;
    }
}

// ------------------------------------------------------------------
extern "C" void kernel_launch(void* const* d_in, const int* in_sizes, int n_in,
                              void* d_out, int out_size) {
    const float* x      = (const float*)d_in[0];
    const float* sw_m   = (const float*)d_in[1];
    const float* sw_v   = (const float*)d_in[2];
    const float* weight = (const float*)d_in[3];
    const float* bias   = (const float*)d_in[4];
    float* out = (float*)d_out;

    stats_kernel<<<NG, 256>>>(x);
    whiten_kernel<<<NG, 256>>>(sw_m, sw_v, weight, bias);
    apply_kernel<<<NG * K3_SPLIT, 256>>>(x, out);
}

// round 10
// speedup vs baseline: 2.0331x; 1.0169x over previous
#include <cuda_runtime.h>
#include <math.h>

#define N_SAMP 32
#define C_TOT 256
#define CPG 16
#define GROUPS 16
#define NG 512
#define HW 4096
#define NHW (N_SAMP * HW)
#define TRI 136
#define STATS_LEN 152          // 16 sums + 136 tri
#define EPS 1e-5f
#define T_ITERS 5

#define K3_SPLIT 4
#define K3_POS (HW / K3_SPLIT)   // 1024

// -------- scratch (device globals) --------
__device__ float g_part[NG][STATS_LEN];   // per-(n,g): [0:16)=sums, [16:152)=tri row-major
__device__ float g_bw[GROUPS][STATS_LEN]; // per-group batch sums
__device__ float g_A[NG][CPG * CPG];
__device__ float g_b0[NG][CPG];

// ------------------------------------------------------------------
// Kernel 1: stats (unchanged from round 9 — 38.4us, proven).
// ------------------------------------------------------------------
__global__ __launch_bounds__(256, 2) void stats_kernel(const float* __restrict__ x) {
    int ng = blockIdx.x;
    int n = ng >> 4;
    int g = ng & 15;
    int tid = threadIdx.x;
    int q = tid >> 6;          // set 0..3
    int t = tid & 63;

    const float* __restrict__ xb = x + (size_t)(n * C_TOT + g * CPG) * HW;

    float s[4];
    float acc[43];
#pragma unroll
    for (int i = 0; i < 4; i++) s[i] = 0.f;
#pragma unroll
    for (int i = 0; i < 43; i++) acc[i] = 0.f;

    if (q == 0) {
#pragma unroll 1
        for (int pass = 0; pass < HW / 256; pass++) {
            int p = pass * 256 + t * 4;
            float4 v[8];
#pragma unroll
            for (int c = 0; c < 8; c++)
                v[c] = *(const float4*)(xb + (size_t)c * HW + p);
#pragma unroll
            for (int c = 0; c < 4; c++) s[c] += (v[c].x + v[c].y) + (v[c].z + v[c].w);
            int idx = 0;
#pragma unroll
            for (int i = 0; i < 8; i++)
#pragma unroll
                for (int j = 0; j <= i; j++) {
                    acc[idx] += v[i].x * v[j].x + v[i].y * v[j].y
                              + v[i].z * v[j].z + v[i].w * v[j].w;
                    idx++;
                }
        }
    } else if (q == 1) {
#pragma unroll 1
        for (int pass = 0; pass < HW / 256; pass++) {
            int p = pass * 256 + t * 4;
            float4 v[11];
#pragma unroll
            for (int c = 0; c < 11; c++)
                v[c] = *(const float4*)(xb + (size_t)c * HW + p);
#pragma unroll
            for (int c = 0; c < 4; c++) s[c] += (v[c + 4].x + v[c + 4].y) + (v[c + 4].z + v[c + 4].w);
            int idx = 0;
#pragma unroll
            for (int i = 8; i < 11; i++)
#pragma unroll
                for (int j = 0; j <= i; j++) {
                    acc[idx] += v[i].x * v[j].x + v[i].y * v[j].y
                              + v[i].z * v[j].z + v[i].w * v[j].w;
                    idx++;
                }
        }
    } else if (q == 2) {
#pragma unroll 1
        for (int pass = 0; pass < HW / 256; pass++) {
            int p = pass * 256 + t * 4;
            float4 v[14];
#pragma unroll
            for (int c = 0; c < 14; c++)
                v[c] = *(const float4*)(xb + (size_t)c * HW + p);
#pragma unroll
            for (int c = 0; c < 4; c++) s[c] += (v[c + 8].x + v[c + 8].y) + (v[c + 8].z + v[c + 8].w);
            int idx = 0;
#pragma unroll
            for (int i = 11; i < 14; i++)
#pragma unroll
                for (int j = 0; j <= i; j++) {
                    acc[idx] += v[i].x * v[j].x + v[i].y * v[j].y
                              + v[i].z * v[j].z + v[i].w * v[j].w;
                    idx++;
                }
        }
    } else {
#pragma unroll 1
        for (int pass = 0; pass < HW / 256; pass++) {
            int p = pass * 256 + t * 4;
            float4 v[16];
#pragma unroll
            for (int c = 0; c < 16; c++)
                v[c] = *(const float4*)(xb + (size_t)c * HW + p);
#pragma unroll
            for (int c = 0; c < 4; c++) s[c] += (v[c + 12].x + v[c + 12].y) + (v[c + 12].z + v[c + 12].w);
            int idx = 0;
#pragma unroll
            for (int i = 14; i < 16; i++)
#pragma unroll
                for (int j = 0; j <= i; j++) {
                    acc[idx] += v[i].x * v[j].x + v[i].y * v[j].y
                              + v[i].z * v[j].z + v[i].w * v[j].w;
                    idx++;
                }
        }
    }

#pragma unroll
    for (int k = 0; k < 4; k++) {
        float v = s[k];
        v += __shfl_xor_sync(0xffffffffu, v, 16);
        v += __shfl_xor_sync(0xffffffffu, v, 8);
        v += __shfl_xor_sync(0xffffffffu, v, 4);
        v += __shfl_xor_sync(0xffffffffu, v, 2);
        v += __shfl_xor_sync(0xffffffffu, v, 1);
        s[k] = v;
    }
#pragma unroll
    for (int k = 0; k < 43; k++) {
        float v = acc[k];
        v += __shfl_xor_sync(0xffffffffu, v, 16);
        v += __shfl_xor_sync(0xffffffffu, v, 8);
        v += __shfl_xor_sync(0xffffffffu, v, 4);
        v += __shfl_xor_sync(0xffffffffu, v, 2);
        v += __shfl_xor_sync(0xffffffffu, v, 1);
        acc[k] = v;
    }

    __shared__ float red[4][2][47];
    int warp = tid >> 5;
    int lane = tid & 31;
    int w2 = warp & 1;
    if (lane == 0) {
#pragma unroll
        for (int k = 0; k < 4; k++) red[q][w2][k] = s[k];
#pragma unroll
        for (int k = 0; k < 43; k++) red[q][w2][4 + k] = acc[k];
    }
    __syncthreads();

    if (tid < 152) {
        int set, loc;
        if (tid < 40)       { set = 0; loc = tid; }
        else if (tid < 74)  { set = 1; loc = tid - 40; }
        else if (tid < 117) { set = 2; loc = tid - 74; }
        else                { set = 3; loc = tid - 117; }
        float a = red[set][0][loc] + red[set][1][loc];
        int dst;
        if (loc < 4) dst = set * 4 + loc;                 // channel sums
        else {
            const int triBase[4] = {16, 52, 82, 121};     // 16 + {0,36,66,105}
            dst = triBase[set] + (loc - 4);
        }
        g_part[ng][dst] = a;
    }
}

// ------------------------------------------------------------------
// Kernel 1b: reduce batch-whitening sums per group ONCE. grid = GROUPS.
// ------------------------------------------------------------------
__global__ __launch_bounds__(256) void bw_kernel() {
    int g = blockIdx.x;
    int t = threadIdx.x;
    if (t < STATS_LEN) {
        float a = 0.f;
#pragma unroll 8
        for (int n = 0; n < N_SAMP; n++)
            a += g_part[n * GROUPS + g][t];
        g_bw[g][t] = a;
    }
}

// ------------------------------------------------------------------
// Kernel 2: mix stats, Newton-Schulz, fold affine.
// Iter 0 analytic (P=I). Double-buffered P: 3 syncs/iter for iters 1-4.
// ------------------------------------------------------------------
__global__ __launch_bounds__(256) void whiten_kernel(
    const float* __restrict__ sw_mean_w,
    const float* __restrict__ sw_var_w,
    const float* __restrict__ weight,
    const float* __restrict__ bias) {

    int ng = blockIdx.x;
    int g = ng & 15;
    int tid = threadIdx.x;
    int i = tid >> 4;
    int j = tid & 15;

    __shared__ float iw[STATS_LEN];
    __shared__ float bw[STATS_LEN];
    __shared__ float M[CPG][CPG + 1];       // covN (never overwritten)
    __shared__ float Pbuf[2][CPG][CPG + 1]; // ping-pong P
    __shared__ float T1[CPG][CPG + 1];
    __shared__ float T2[CPG][CPG + 1];
    __shared__ float meanmix[CPG];

    if (tid < STATS_LEN) {
        iw[tid] = g_part[ng][tid];
        bw[tid] = g_bw[g][tid];
    }
    __syncthreads();

    int a_ = i > j ? i : j;
    int b_ = i > j ? j : i;
    int t = a_ * (a_ + 1) / 2 + b_;

    float sin_ij = iw[16 + t];
    float mi_i = iw[i] * (1.0f / HW);
    float mi_j = iw[j] * (1.0f / HW);
    float sbn = bw[16 + t];
    float mb_i = bw[i] * (1.0f / NHW);
    float mb_j = bw[j] * (1.0f / NHW);

    float cov_in = sin_ij * (1.0f / HW) - mi_i * mi_j;
    float cov_bn = sbn * (1.0f / NHW) - mb_i * mb_j;

    float w0 = sw_mean_w[0], w1 = sw_mean_w[1];
    float mm = fmaxf(w0, w1);
    float e0 = expf(w0 - mm), e1 = expf(w1 - mm);
    float mw0 = e0 / (e0 + e1);
    float mw1 = 1.0f - mw0;

    float v0 = sw_var_w[0], v1 = sw_var_w[1];
    float vm = fmaxf(v0, v1);
    float f0 = expf(v0 - vm), f1 = expf(v1 - vm);
    float vw0 = f0 / (f0 + f1);
    float vw1 = 1.0f - vw0;

    float cval = vw0 * cov_bn + vw1 * cov_in + (i == j ? EPS : 0.0f);
    M[i][j] = cval;                       // temporarily raw cov for trace
    if (i == 0) meanmix[j] = mw0 * mb_j + mw1 * mi_j;
    __syncthreads();

    float tr = 0.f;
#pragma unroll
    for (int k = 0; k < CPG; k++) tr += M[k][k];
    float rTr = 1.0f / tr;
    __syncthreads();   // finish trace reads before overwrite

    float covN_ij = cval * rTr;
    M[i][j] = covN_ij;
    // Iter 0 analytic: P1 = 1.5 I - 0.5 covN   (since P=I => P^3 covN = covN)
    Pbuf[0][i][j] = (i == j ? 1.5f : 0.0f) - 0.5f * covN_ij;
    __syncthreads();

    int cur = 0;
    for (int iter = 1; iter < T_ITERS; iter++) {
        float acc = 0.f;
#pragma unroll
        for (int k = 0; k < CPG; k++) acc += Pbuf[cur][i][k] * Pbuf[cur][k][j];
        T1[i][j] = acc;
        __syncthreads();

        acc = 0.f;
#pragma unroll
        for (int k = 0; k < CPG; k++) acc += T1[i][k] * Pbuf[cur][k][j];
        T2[i][j] = acc;
        __syncthreads();

        acc = 0.f;
#pragma unroll
        for (int k = 0; k < CPG; k++) acc += T2[i][k] * M[k][j];
        Pbuf[1 - cur][i][j] = 1.5f * Pbuf[cur][i][j] - 0.5f * acc;
        __syncthreads();
        cur = 1 - cur;
    }

    float wm_ij = Pbuf[cur][i][j] * sqrtf(rTr);
    T1[i][j] = wm_ij;
    float A_ij = weight[g * CPG + i] * wm_ij;
    g_A[ng][i * CPG + j] = A_ij;
    __syncthreads();

    if (tid < CPG) {
        int c = tid;
        float wc = weight[g * CPG + c];
        float acc = 0.f;
#pragma unroll
        for (int d = 0; d < CPG; d++) acc += T1[c][d] * meanmix[d];
        g_b0[ng][c] = bias[g * CPG + c] - wc * acc;
    }
}

// ------------------------------------------------------------------
// Kernel 3: apply (unchanged — 39.4us, 68% DRAM).
// ------------------------------------------------------------------
__global__ __launch_bounds__(256) void apply_kernel(const float* __restrict__ x,
                                                    float* __restrict__ out) {
    int b = blockIdx.x;
    int ng = b >> 2;                 // / K3_SPLIT
    int chunk = b & (K3_SPLIT - 1);
    int n = ng >> 4;
    int g = ng & 15;
    int tid = threadIdx.x;

    __shared__ float sA[CPG][CPG];
    __shared__ float sb[CPG];
    sA[tid >> 4][tid & 15] = g_A[ng][tid];
    if (tid < CPG) sb[tid] = g_b0[ng][tid];
    __syncthreads();

    size_t base = (size_t)(n * C_TOT + g * CPG) * HW
                + (size_t)chunk * K3_POS + (size_t)tid * 4;

    float4 v[CPG];
#pragma unroll
    for (int d = 0; d < CPG; d++)
        v[d] = *(const float4*)(x + base + (size_t)d * HW);

#pragma unroll
    for (int c = 0; c < CPG; c++) {
        float bc = sb[c];
        float4 acc = make_float4(bc, bc, bc, bc);
#pragma unroll
        for (int d = 0; d < CPG; d++) {
            float a = sA[c][d];
            acc.x += a * v[d].x;
            acc.y += a * v[d].y;
            acc.z += a * v[d].z;
            acc.w += a * v[d].w;
        }
        *(float4*)(out + base + (size_t)c * HW) = acc;
    }
}

// ------------------------------------------------------------------
extern "C" void kernel_launch(void* const* d_in, const int* in_sizes, int n_in,
                              void* d_out, int out_size) {
    const float* x      = (const float*)d_in[0];
    const float* sw_m   = (const float*)d_in[1];
    const float* sw_v   = (const float*)d_in[2];
    const float* weight = (const float*)d_in[3];
    const float* bias   = (const float*)d_in[4];
    float* out = (float*)d_out;

    stats_kernel<<<NG, 256>>>(x);
    bw_kernel<<<GROUPS, 256>>>();
    whiten_kernel<<<NG, 256>>>(sw_m, sw_v, weight, bias);
    apply_kernel<<<NG * K3_SPLIT, 256>>>(x, out);
}